// round 6
// baseline (speedup 1.0000x reference)
#include <cuda_runtime.h>

// DDA_PU_loss: loss = sum_pos (recon-dv)^2 * (1-alpha)/2 + sum_neg (recon-dv)^2 * alpha/2
// Inputs (metadata order):
//  0: drug_virus_reconstruct f32 [8192,16384]
//  1: drug_virus             f32 [8192,16384]
//  2: drug_virus_mask        f32 (unused by reference math)
//  3: pos_x_index  [524288]   int32 OR int64 (detected at runtime)
//  4: pos_y_index  [524288]
//  5: neg_x_index  [2097152]
//  6: neg_y_index  [2097152]
//  7: alpha        f32 scalar
// Output: f32 scalar.

#define N_VIRUS_LOG2 14  // row width 16384, fixed shape

__device__ double g_acc[2];  // [0]=pos_se, [1]=neg_se
__device__ int    g_is64;    // 1 if index arrays are int64, 0 if int32

// Detect index dtype: for int64 little-endian nonnegative values < 2^13,
// every odd 32-bit word (high half) is zero. For int32 uniform in [0,8192),
// the chance all 128 sampled odd words are zero is (1/8192)^128 ~ 0.
__global__ void setup_kernel(const unsigned* __restrict__ px_words) {
    if (threadIdx.x == 0) {
        int all_zero = 1;
        #pragma unroll 1
        for (int i = 1; i < 256; i += 2) all_zero &= (px_words[i] == 0u);
        g_is64  = all_zero;
        g_acc[0] = 0.0;
        g_acc[1] = 0.0;
    }
}

__global__ __launch_bounds__(256) void gather_se_kernel(
    const float* __restrict__ recon,
    const float* __restrict__ dv,
    const void*  __restrict__ px_raw,
    const void*  __restrict__ py_raw,
    int n_pos,
    const void*  __restrict__ nx_raw,
    const void*  __restrict__ ny_raw,
    int n_neg)
{
    const int tid    = blockIdx.x * blockDim.x + threadIdx.x;
    const int stride = gridDim.x * blockDim.x;
    const int is64   = g_is64;  // uniform across grid

    double pos_acc = 0.0;
    double neg_acc = 0.0;

    if (!is64) {
        const int* __restrict__ px = (const int*)px_raw;
        const int* __restrict__ py = (const int*)py_raw;
        const int* __restrict__ nx = (const int*)nx_raw;
        const int* __restrict__ ny = (const int*)ny_raw;

        for (int i = tid; i < n_pos; i += stride) {
            unsigned idx = ((unsigned)__ldg(&px[i]) << N_VIRUS_LOG2) + (unsigned)__ldg(&py[i]);
            float d = __ldg(&recon[idx]) - __ldg(&dv[idx]);
            pos_acc += (double)d * (double)d;
        }
        for (int i = tid; i < n_neg; i += stride) {
            unsigned idx = ((unsigned)__ldg(&nx[i]) << N_VIRUS_LOG2) + (unsigned)__ldg(&ny[i]);
            float d = __ldg(&recon[idx]) - __ldg(&dv[idx]);
            neg_acc += (double)d * (double)d;
        }
    } else {
        const long long* __restrict__ px = (const long long*)px_raw;
        const long long* __restrict__ py = (const long long*)py_raw;
        const long long* __restrict__ nx = (const long long*)nx_raw;
        const long long* __restrict__ ny = (const long long*)ny_raw;

        for (int i = tid; i < n_pos; i += stride) {
            long long idx = (__ldg(&px[i]) << N_VIRUS_LOG2) + __ldg(&py[i]);
            float d = __ldg(&recon[idx]) - __ldg(&dv[idx]);
            pos_acc += (double)d * (double)d;
        }
        for (int i = tid; i < n_neg; i += stride) {
            long long idx = (__ldg(&nx[i]) << N_VIRUS_LOG2) + __ldg(&ny[i]);
            float d = __ldg(&recon[idx]) - __ldg(&dv[idx]);
            neg_acc += (double)d * (double)d;
        }
    }

    // warp reduction
    #pragma unroll
    for (int off = 16; off > 0; off >>= 1) {
        pos_acc += __shfl_down_sync(0xFFFFFFFFu, pos_acc, off);
        neg_acc += __shfl_down_sync(0xFFFFFFFFu, neg_acc, off);
    }
    if ((threadIdx.x & 31) == 0) {
        atomicAdd(&g_acc[0], pos_acc);
        atomicAdd(&g_acc[1], neg_acc);
    }
}

__global__ void finalize_kernel(const float* __restrict__ alpha, float* __restrict__ out) {
    double a = (double)alpha[0];
    out[0] = (float)(g_acc[0] * ((1.0 - a) * 0.5) + g_acc[1] * (a * 0.5));
}

extern "C" void kernel_launch(void* const* d_in, const int* in_sizes, int n_in,
                              void* d_out, int out_size)
{
    const float* recon = (const float*)d_in[0];
    const float* dv    = (const float*)d_in[1];
    const void*  px    = d_in[3];
    const void*  py    = d_in[4];
    const void*  nx    = d_in[5];
    const void*  ny    = d_in[6];
    const float* alpha = (const float*)d_in[7];
    float*       out   = (float*)d_out;

    int n_pos = in_sizes[3];
    int n_neg = in_sizes[5];

    setup_kernel<<<1, 32>>>((const unsigned*)px);

    const int threads = 256;
    const int blocks  = 148 * 16;  // ~606K threads
    gather_se_kernel<<<blocks, threads>>>(recon, dv, px, py, n_pos, nx, ny, n_neg);

    finalize_kernel<<<1, 1>>>(alpha, out);
}